// round 1
// baseline (speedup 1.0000x reference)
#include <cuda_runtime.h>

#define BATCH 16
#define TLEN  4096
#define DIM   512
#define NROWS (BATCH*TLEN)    // 65536 rows, time-major: r = t*B + b
#define TG    16              // time steps per group
#define GROWS (TG*BATCH)      // 256 rows per group
#define NG    (TLEN/TG)       // 256 groups
#define DD2   (DIM*DIM)       // 262144
#define GR2   (GROWS*GROWS)   // 65536
#define LRW   0.01f

// Scratch (device globals — no allocation in kernel_launch)
__device__ float g_Q[NROWS*DIM];   // 134 MB, time-major [r][e]
__device__ float g_K[NROWS*DIM];
__device__ float g_V[NROWS*DIM];
__device__ float g_S[(size_t)NG*DD2];    // 268 MB: U_g, then scanned in place -> S_g (group-start states)
__device__ float g_Sc[(size_t)NG*GR2];   // 67 MB: masked scores * LR

// ---------------------------------------------------------------------------
// Common micro-kernel: 64x64 C tile, 256 threads (16x16), 4x4 per thread,
// BK=16, smem padded to 68 floats/row so float4 smem accesses stay 16B-aligned.
// ---------------------------------------------------------------------------

#define MICRO_FMA(As, Bs, acc, tx, ty)                                  \
  _Pragma("unroll")                                                     \
  for (int kk = 0; kk < 16; kk++) {                                     \
    float4 a = *(const float4*)(&As[kk][(ty)*4]);                       \
    float4 b = *(const float4*)(&Bs[kk][(tx)*4]);                       \
    float ar[4] = {a.x, a.y, a.z, a.w};                                 \
    float br[4] = {b.x, b.y, b.z, b.w};                                 \
    _Pragma("unroll")                                                   \
    for (int i = 0; i < 4; i++)                                         \
      _Pragma("unroll")                                                 \
      for (int j = 0; j < 4; j++)                                       \
        acc[i][j] = fmaf(ar[i], br[j], acc[i][j]);                      \
  }

// ---------------------------------------------------------------------------
// 1) QKV projections: C[r,e] = sum_d Xrow(r)[d] * W[e,d]
//    Output time-major into g_Q/g_K/g_V; blockIdx.z selects which projection.
// ---------------------------------------------------------------------------
__global__ __launch_bounds__(256) void qkv_kernel(
    const float* __restrict__ x,
    const float* __restrict__ Wq, const float* __restrict__ Wk,
    const float* __restrict__ Wv) {
  __shared__ float As[16][68];
  __shared__ float Bs[16][68];
  int r0 = blockIdx.x * 64;
  int c0 = blockIdx.y * 64;
  const float* W  = (blockIdx.z == 0) ? Wq : (blockIdx.z == 1) ? Wk : Wv;
  float*       Co = (blockIdx.z == 0) ? g_Q : (blockIdx.z == 1) ? g_K : g_V;

  int tid = threadIdx.x;
  int tx = tid & 15, ty = tid >> 4;
  int lrow = tid >> 2;          // 0..63
  int lk4  = (tid & 3) * 4;     // 0,4,8,12

  // A row remap: time-major row r -> x[b,t,:]
  int gr = r0 + lrow;
  int tt = gr >> 4, bb = gr & 15;
  const float* arow = x + (size_t)(bb * TLEN + tt) * DIM;
  const float* brow = W + (size_t)(c0 + lrow) * DIM;

  float acc[4][4] = {};
  for (int k0 = 0; k0 < DIM; k0 += 16) {
    float4 av = *(const float4*)(arow + k0 + lk4);
    float4 bv = *(const float4*)(brow + k0 + lk4);
    __syncthreads();
    As[lk4+0][lrow] = av.x; As[lk4+1][lrow] = av.y;
    As[lk4+2][lrow] = av.z; As[lk4+3][lrow] = av.w;
    Bs[lk4+0][lrow] = bv.x; Bs[lk4+1][lrow] = bv.y;
    Bs[lk4+2][lrow] = bv.z; Bs[lk4+3][lrow] = bv.w;
    __syncthreads();
    MICRO_FMA(As, Bs, acc, tx, ty)
  }
#pragma unroll
  for (int i = 0; i < 4; i++) {
    int row = r0 + ty * 4 + i;
    float4 v = make_float4(acc[i][0], acc[i][1], acc[i][2], acc[i][3]);
    *(float4*)(Co + (size_t)row * DIM + c0 + tx * 4) = v;
  }
}

// ---------------------------------------------------------------------------
// 2) Per-group U_g[d,e] = sum_{r in group} V[r,d] * K[r,e]   (TN gemm, K=256)
// ---------------------------------------------------------------------------
__global__ __launch_bounds__(256) void u_kernel() {
  __shared__ float As[16][68];
  __shared__ float Bs[16][68];
  int d0 = blockIdx.x * 64;
  int e0 = blockIdx.y * 64;
  int g  = blockIdx.z;
  int gbase = g * GROWS;
  int tid = threadIdx.x;
  int tx = tid & 15, ty = tid >> 4;
  int lk  = tid >> 4;            // 0..15
  int lc4 = (tid & 15) * 4;      // 0..60

  float acc[4][4] = {};
  for (int k0 = 0; k0 < GROWS; k0 += 16) {
    int rrow = gbase + k0 + lk;
    float4 av = *(const float4*)(g_V + (size_t)rrow * DIM + d0 + lc4);
    float4 bv = *(const float4*)(g_K + (size_t)rrow * DIM + e0 + lc4);
    __syncthreads();
    *(float4*)(&As[lk][lc4]) = av;
    *(float4*)(&Bs[lk][lc4]) = bv;
    __syncthreads();
    MICRO_FMA(As, Bs, acc, tx, ty)
  }
  float* U = g_S + (size_t)g * DD2;
#pragma unroll
  for (int i = 0; i < 4; i++) {
    float4 v = make_float4(acc[i][0], acc[i][1], acc[i][2], acc[i][3]);
    *(float4*)(U + (size_t)(d0 + ty * 4 + i) * DIM + e0 + tx * 4) = v;
  }
}

// ---------------------------------------------------------------------------
// 3) Exclusive prefix scan over groups (elementwise): S_g = m0 + LR*sum_{g'<g} U_g'
// ---------------------------------------------------------------------------
__global__ void scan_kernel(const float* __restrict__ mem0) {
  int idx = blockIdx.x * blockDim.x + threadIdx.x;
  float acc = mem0[idx];
  for (int g = 0; g < NG; g++) {
    size_t off = (size_t)g * DD2 + idx;
    float u = g_S[off];
    g_S[off] = acc;
    acc = fmaf(LRW, u, acc);
  }
}

// ---------------------------------------------------------------------------
// 4) Inter term: out[r,d] = sum_e Q[r,e] * S_g[d,e]  (NT gemm, plain store)
// ---------------------------------------------------------------------------
__global__ __launch_bounds__(256) void inter_kernel(float* __restrict__ out) {
  __shared__ float As[16][68];
  __shared__ float Bs[16][68];
  int r0 = blockIdx.x * 64;
  int c0 = blockIdx.y * 64;
  int g  = r0 / GROWS;
  const float* Sg = g_S + (size_t)g * DD2;

  int tid = threadIdx.x;
  int tx = tid & 15, ty = tid >> 4;
  int lrow = tid >> 2;
  int lk4  = (tid & 3) * 4;
  const float* arow = g_Q + (size_t)(r0 + lrow) * DIM;
  const float* brow = Sg + (size_t)(c0 + lrow) * DIM;

  float acc[4][4] = {};
  for (int k0 = 0; k0 < DIM; k0 += 16) {
    float4 av = *(const float4*)(arow + k0 + lk4);
    float4 bv = *(const float4*)(brow + k0 + lk4);
    __syncthreads();
    As[lk4+0][lrow] = av.x; As[lk4+1][lrow] = av.y;
    As[lk4+2][lrow] = av.z; As[lk4+3][lrow] = av.w;
    Bs[lk4+0][lrow] = bv.x; Bs[lk4+1][lrow] = bv.y;
    Bs[lk4+2][lrow] = bv.z; Bs[lk4+3][lrow] = bv.w;
    __syncthreads();
    MICRO_FMA(As, Bs, acc, tx, ty)
  }
#pragma unroll
  for (int i = 0; i < 4; i++) {
    int gr = r0 + ty * 4 + i;
    int tt = gr >> 4, bb = gr & 15;
    float4 v = make_float4(acc[i][0], acc[i][1], acc[i][2], acc[i][3]);
    *(float4*)(out + (size_t)(bb * TLEN + tt) * DIM + c0 + tx * 4) = v;
  }
}

// ---------------------------------------------------------------------------
// 5a) Intra scores (lower-triangular 64x64 tiles only):
//     Sc[rr,ss] = LR * (Q[gr]·K[gs]) masked by floor(ss/16) <= floor(rr/16)
// ---------------------------------------------------------------------------
__global__ __launch_bounds__(256) void score_kernel() {
  __shared__ float As[16][68];
  __shared__ float Bs[16][68];
  int id = blockIdx.x;  // 0..9 -> lower-tri tile (ti,tj)
  int ti, base;
  if (id < 1)      { ti = 0; base = 0; }
  else if (id < 3) { ti = 1; base = 1; }
  else if (id < 6) { ti = 2; base = 3; }
  else             { ti = 3; base = 6; }
  int tj = id - base;
  int g = blockIdx.y;
  int gbase = g * GROWS;
  int r0 = ti * 64, s0 = tj * 64;   // local within group

  int tid = threadIdx.x;
  int tx = tid & 15, ty = tid >> 4;
  int lrow = tid >> 2;
  int lk4  = (tid & 3) * 4;
  const float* arow = g_Q + (size_t)(gbase + r0 + lrow) * DIM;
  const float* brow = g_K + (size_t)(gbase + s0 + lrow) * DIM;

  float acc[4][4] = {};
  for (int k0 = 0; k0 < DIM; k0 += 16) {
    float4 av = *(const float4*)(arow + k0 + lk4);
    float4 bv = *(const float4*)(brow + k0 + lk4);
    __syncthreads();
    As[lk4+0][lrow] = av.x; As[lk4+1][lrow] = av.y;
    As[lk4+2][lrow] = av.z; As[lk4+3][lrow] = av.w;
    Bs[lk4+0][lrow] = bv.x; Bs[lk4+1][lrow] = bv.y;
    Bs[lk4+2][lrow] = bv.z; Bs[lk4+3][lrow] = bv.w;
    __syncthreads();
    MICRO_FMA(As, Bs, acc, tx, ty)
  }
  float* Sc = g_Sc + (size_t)g * GR2;
#pragma unroll
  for (int i = 0; i < 4; i++) {
    int rr = r0 + ty * 4 + i;
    float v[4];
#pragma unroll
    for (int j = 0; j < 4; j++) {
      int ss = s0 + tx * 4 + j;
      v[j] = ((ss >> 4) <= (rr >> 4)) ? LRW * acc[i][j] : 0.0f;
    }
    *(float4*)(Sc + (size_t)rr * GROWS + s0 + tx * 4) =
        make_float4(v[0], v[1], v[2], v[3]);
  }
}

// ---------------------------------------------------------------------------
// 5b) Intra AV: out[r,d] += sum_{s < (ti+1)*64} Sc[rr,ss] * V[gs,d]
// ---------------------------------------------------------------------------
__global__ __launch_bounds__(256) void av_kernel(float* __restrict__ out) {
  __shared__ float As[16][68];
  __shared__ float Bs[16][68];
  int bx = blockIdx.x;
  int g  = bx >> 2;
  int ti = bx & 3;
  int d0 = blockIdx.y * 64;
  int gbase = g * GROWS;
  int r0 = ti * 64;
  int klen = (ti + 1) * 64;     // causal: only keys up to end of this row tile
  const float* A = g_Sc + (size_t)g * GR2;

  int tid = threadIdx.x;
  int tx = tid & 15, ty = tid >> 4;
  int lrowA = tid >> 2;
  int lk4   = (tid & 3) * 4;
  int lkB   = tid >> 4;
  int lc4   = (tid & 15) * 4;

  float acc[4][4] = {};
  for (int k0 = 0; k0 < klen; k0 += 16) {
    float4 av = *(const float4*)(A + (size_t)(r0 + lrowA) * GROWS + k0 + lk4);
    float4 bv = *(const float4*)(g_V + (size_t)(gbase + k0 + lkB) * DIM + d0 + lc4);
    __syncthreads();
    As[lk4+0][lrowA] = av.x; As[lk4+1][lrowA] = av.y;
    As[lk4+2][lrowA] = av.z; As[lk4+3][lrowA] = av.w;
    *(float4*)(&Bs[lkB][lc4]) = bv;
    __syncthreads();
    MICRO_FMA(As, Bs, acc, tx, ty)
  }
#pragma unroll
  for (int i = 0; i < 4; i++) {
    int gr = gbase + r0 + ty * 4 + i;
    int tt = gr >> 4, bb = gr & 15;
    float4* p = (float4*)(out + (size_t)(bb * TLEN + tt) * DIM + d0 + tx * 4);
    float4 o = *p;
    o.x += acc[i][0]; o.y += acc[i][1]; o.z += acc[i][2]; o.w += acc[i][3];
    *p = o;
  }
}

// ---------------------------------------------------------------------------
extern "C" void kernel_launch(void* const* d_in, const int* in_sizes, int n_in,
                              void* d_out, int out_size) {
  (void)in_sizes; (void)n_in; (void)out_size;
  const float* x   = (const float*)d_in[0];
  const float* Wq  = (const float*)d_in[1];
  const float* Wk  = (const float*)d_in[2];
  const float* Wv  = (const float*)d_in[3];
  const float* m0  = (const float*)d_in[4];
  float* out = (float*)d_out;

  qkv_kernel  <<<dim3(NROWS/64, DIM/64, 3), 256>>>(x, Wq, Wk, Wv);
  u_kernel    <<<dim3(DIM/64, DIM/64, NG), 256>>>();
  scan_kernel <<<DD2/256, 256>>>(m0);
  inter_kernel<<<dim3(NROWS/64, DIM/64), 256>>>(out);
  score_kernel<<<dim3(10, NG), 256>>>();
  av_kernel   <<<dim3(4*NG, DIM/64), 256>>>(out);
}

// round 7
// speedup vs baseline: 1.2392x; 1.2392x over previous
#include <cuda_runtime.h>
#include <cuda_bf16.h>
#include <mma.h>
#include <cstdint>

typedef __nv_bfloat16 bf;
typedef __nv_bfloat162 bf2;
namespace wm = nvcuda::wmma;
using AccFrag = wm::fragment<wm::accumulator, 16, 16, 16, float>;

#define BATCH 16
#define TLEN  4096
#define DIM   512
#define NROWS 65536              // time-major rows r = t*16 + b
#define GROWS 256                // rows per group (16 t-steps x 16 batch)
#define NG    256
#define DD2   (DIM*DIM)          // 262144
#define GR2   (GROWS*GROWS)
#define LRW   0.01f

// ---------------- device scratch ----------------
__device__ __align__(256) bf g_Xh[(size_t)NROWS*DIM];
__device__ __align__(256) bf g_Xl[(size_t)NROWS*DIM];
__device__ __align__(256) bf g_Wh[3*DD2];
__device__ __align__(256) bf g_Wl[3*DD2];
__device__ __align__(256) bf g_Qh[(size_t)NROWS*DIM];
__device__ __align__(256) bf g_Ql[(size_t)NROWS*DIM];
__device__ __align__(256) bf g_Kh[(size_t)NROWS*DIM];
__device__ __align__(256) bf g_Kl[(size_t)NROWS*DIM];
__device__ __align__(256) bf g_Vh[(size_t)NROWS*DIM];
__device__ __align__(256) bf g_Vl[(size_t)NROWS*DIM];
__device__ __align__(256) bf g_Kth[(size_t)DIM*NROWS];
__device__ __align__(256) bf g_Ktl[(size_t)DIM*NROWS];
__device__ __align__(256) bf g_Vth[(size_t)DIM*NROWS];
__device__ __align__(256) bf g_Vtl[(size_t)DIM*NROWS];
__device__ __align__(256) float g_U[(size_t)NG*DD2];
__device__ __align__(256) bf g_Sh[(size_t)NG*DD2];
__device__ __align__(256) bf g_Sl[(size_t)NG*DD2];
__device__ __align__(256) bf g_Sch[(size_t)NG*GR2];
__device__ __align__(256) bf g_Scl[(size_t)NG*GR2];

// ---------------------------------------------------------------------------
// Generic 128x128 NT GEMM core with wmma bf16 hi/lo 3-pass, BK=16.
// A, B row-major K-contiguous, pre-offset to tile origin.
// 256 threads, 8 warps in 2x4, warp tile 64x32 = 4x2 fragments.
// ---------------------------------------------------------------------------
__device__ __forceinline__ void gemm_core(
    const bf* __restrict__ Ah, const bf* __restrict__ Al, size_t lda,
    const bf* __restrict__ Bh, const bf* __restrict__ Bl, size_t ldb,
    int nktp, AccFrag acc[4][2])
{
    __shared__ bf As[128 * 24];
    __shared__ bf Bs[128 * 24];
    const int tid  = threadIdx.x;
    const int lane = tid & 31;
    const int w    = tid >> 5;
    const int wm   = w >> 2, wn = w & 3;
    const int row  = tid >> 1;       // 0..127
    const int half = tid & 1;        // 8-bf (16B) chunk
    const int nIter = nktp * 3;
    (void)lane;

#pragma unroll
    for (int mt = 0; mt < 4; mt++)
#pragma unroll
        for (int n2 = 0; n2 < 2; n2++)
            wm::fill_fragment(acc[mt][n2], 0.0f);

    for (int it = 0; it < nIter; ++it) {
        int p  = it / nktp;
        int kt = it - p * nktp;
        const bf* A = (p == 1) ? Al : Ah;
        const bf* B = (p == 2) ? Bl : Bh;
        uint4 av = *(const uint4*)(A + (size_t)row * lda + kt * 16 + half * 8);
        uint4 bv = *(const uint4*)(B + (size_t)row * ldb + kt * 16 + half * 8);
        __syncthreads();   // previous tile fully consumed
        *(uint4*)(&As[row * 24 + half * 8]) = av;
        *(uint4*)(&Bs[row * 24 + half * 8]) = bv;
        __syncthreads();

        wm::fragment<wm::matrix_a, 16, 16, 16, bf, wm::row_major> af[4];
        wm::fragment<wm::matrix_b, 16, 16, 16, bf, wm::col_major> bfr[2];
#pragma unroll
        for (int mt = 0; mt < 4; mt++)
            wm::load_matrix_sync(af[mt], &As[(wm * 64 + mt * 16) * 24], 24);
#pragma unroll
        for (int n2 = 0; n2 < 2; n2++)
            wm::load_matrix_sync(bfr[n2], &Bs[(wn * 32 + n2 * 16) * 24], 24);
#pragma unroll
        for (int mt = 0; mt < 4; mt++)
#pragma unroll
            for (int n2 = 0; n2 < 2; n2++)
                wm::mma_sync(acc[mt][n2], af[mt], bfr[n2], acc[mt][n2]);
    }
    __syncthreads();
}

__device__ __forceinline__ float* warp_stage() {
    __shared__ float st[8][320];      // per-warp 16x20 staging
    return st[threadIdx.x >> 5];
}

// Epilogue: stage each frag, then scalar writes. Variadic (commas OK).
// Exposes: row (0..127 tile-local), col (0..127 tile-local), v (float).
#define EPILOGUE(...)                                                     \
  { float* stg = warp_stage();                                            \
    const int lane = threadIdx.x & 31;                                    \
    const int w = threadIdx.x >> 5, wm_ = w >> 2, wn_ = w & 3;            \
    for (int mt = 0; mt < 4; mt++)                                        \
      for (int n2 = 0; n2 < 2; n2++) {                                    \
        wm::store_matrix_sync(stg, acc[mt][n2], 20, wm::mem_row_major);   \
        __syncwarp();                                                     \
        _Pragma("unroll")                                                 \
        for (int e = 0; e < 8; e++) {                                     \
          int lr = 2 * e + (lane >> 4); int lc = lane & 15;               \
          int row = wm_ * 64 + mt * 16 + lr;                              \
          int col = wn_ * 32 + n2 * 16 + lc;                              \
          float v = stg[lr * 20 + lc];                                    \
          __VA_ARGS__                                                     \
        }                                                                 \
        __syncwarp();                                                     \
      } }

__device__ __forceinline__ void split1(bf* Oh, bf* Ol, size_t idx, float v) {
    bf h = __float2bfloat16(v);
    Oh[idx] = h;
    Ol[idx] = __float2bfloat16(v - __bfloat162float(h));
}
__device__ __forceinline__ void split_store(bf* Oh, bf* Ol, size_t idx,
                                            float v0, float v1) {
    bf h0 = __float2bfloat16(v0), h1 = __float2bfloat16(v1);
    bf2 ph; ph.x = h0; ph.y = h1;
    bf2 pl; pl.x = __float2bfloat16(v0 - __bfloat162float(h0));
            pl.y = __float2bfloat16(v1 - __bfloat162float(h1));
    *(bf2*)(Oh + idx) = ph;
    *(bf2*)(Ol + idx) = pl;
}

// ---------------- conversion / transpose / scan ----------------------------
__global__ void conv_x_kernel(const float* __restrict__ x) {
    int i = blockIdx.x * 256 + threadIdx.x;       // over NROWS*DIM/4
    int r = i >> 7;
    int d = (i & 127) * 4;
    int tt = r >> 4, bb = r & 15;
    float4 v = *(const float4*)(x + (size_t)(bb * TLEN + tt) * DIM + d);
    size_t o = (size_t)r * DIM + d;
    split_store(g_Xh, g_Xl, o,     v.x, v.y);
    split_store(g_Xh, g_Xl, o + 2, v.z, v.w);
}

__global__ void conv_w_kernel(const float* __restrict__ Wq,
                              const float* __restrict__ Wk,
                              const float* __restrict__ Wv) {
    int i = blockIdx.x * 256 + threadIdx.x;       // over 3*DD2/4
    int z = i >> 16;
    int off = (i & 65535) * 4;
    const float* src = (z == 0) ? Wq : (z == 1) ? Wk : Wv;
    float4 v = *(const float4*)(src + off);
    size_t o = (size_t)z * DD2 + off;
    split_store(g_Wh, g_Wl, o,     v.x, v.y);
    split_store(g_Wh, g_Wl, o + 2, v.z, v.w);
}

__global__ void transpose_kernel() {  // grid (1024, 8, 4), block (64, 8)
    __shared__ bf t[64][65];
    int r0 = blockIdx.x * 64, d0 = blockIdx.y * 64, z = blockIdx.z;
    const bf* src = (z == 0) ? g_Kh : (z == 1) ? g_Kl : (z == 2) ? g_Vh : g_Vl;
    bf* dst = (z == 0) ? g_Kth : (z == 1) ? g_Ktl : (z == 2) ? g_Vth : g_Vtl;
    for (int ry = threadIdx.y; ry < 64; ry += 8)
        t[ry][threadIdx.x] = src[(size_t)(r0 + ry) * DIM + d0 + threadIdx.x];
    __syncthreads();
    for (int dy = threadIdx.y; dy < 64; dy += 8)
        dst[(size_t)(d0 + dy) * NROWS + r0 + threadIdx.x] = t[threadIdx.x][dy];
}

__global__ void scan_kernel(const float* __restrict__ mem0) {
    int i4 = (blockIdx.x * 256 + threadIdx.x) * 4;    // over DD2
    float4 acc = *(const float4*)(mem0 + i4);
    for (int g = 0; g < NG; g++) {
        size_t off = (size_t)g * DD2 + i4;
        float4 u = *(const float4*)(g_U + off);
        split_store(g_Sh, g_Sl, off,     acc.x, acc.y);
        split_store(g_Sh, g_Sl, off + 2, acc.z, acc.w);
        acc.x = fmaf(LRW, u.x, acc.x);
        acc.y = fmaf(LRW, u.y, acc.y);
        acc.z = fmaf(LRW, u.z, acc.z);
        acc.w = fmaf(LRW, u.w, acc.w);
    }
}

// ---------------- GEMM kernels ---------------------------------------------
__global__ __launch_bounds__(256) void gemm_qkv_kernel() {
    int mt0 = blockIdx.x, nt0 = blockIdx.y, z = blockIdx.z;
    const bf* Ah = g_Xh + (size_t)mt0 * 128 * DIM;
    const bf* Al = g_Xl + (size_t)mt0 * 128 * DIM;
    const bf* Bh = g_Wh + (size_t)z * DD2 + (size_t)nt0 * 128 * DIM;
    const bf* Bl = g_Wl + (size_t)z * DD2 + (size_t)nt0 * 128 * DIM;
    AccFrag acc[4][2];
    gemm_core(Ah, Al, DIM, Bh, Bl, DIM, DIM / 16, acc);
    bf* Oh = (z == 0) ? g_Qh : (z == 1) ? g_Kh : g_Vh;
    bf* Ol = (z == 0) ? g_Ql : (z == 1) ? g_Kl : g_Vl;
    EPILOGUE(
        size_t idx = (size_t)(mt0 * 128 + row) * DIM + nt0 * 128 + col;
        split1(Oh, Ol, idx, v);
    )
}

__global__ __launch_bounds__(256) void gemm_u_kernel() {
    int d0 = blockIdx.x * 128, e0 = blockIdx.y * 128, g = blockIdx.z;
    const bf* Ah = g_Vth + (size_t)d0 * NROWS + g * GROWS;
    const bf* Al = g_Vtl + (size_t)d0 * NROWS + g * GROWS;
    const bf* Bh = g_Kth + (size_t)e0 * NROWS + g * GROWS;
    const bf* Bl = g_Ktl + (size_t)e0 * NROWS + g * GROWS;
    AccFrag acc[4][2];
    gemm_core(Ah, Al, NROWS, Bh, Bl, NROWS, GROWS / 16, acc);
    float* U = g_U + (size_t)g * DD2;
    EPILOGUE(
        U[(size_t)(d0 + row) * DIM + e0 + col] = v;
    )
}

__global__ __launch_bounds__(256) void gemm_inter_kernel(float* __restrict__ out) {
    int mt0 = blockIdx.x, nt0 = blockIdx.y;
    int g = mt0 >> 1;
    const bf* Ah = g_Qh + (size_t)mt0 * 128 * DIM;
    const bf* Al = g_Ql + (size_t)mt0 * 128 * DIM;
    const bf* Bh = g_Sh + (size_t)g * DD2 + (size_t)nt0 * 128 * DIM;
    const bf* Bl = g_Sl + (size_t)g * DD2 + (size_t)nt0 * 128 * DIM;
    AccFrag acc[4][2];
    gemm_core(Ah, Al, DIM, Bh, Bl, DIM, DIM / 16, acc);
    EPILOGUE(
        int r = mt0 * 128 + row;
        int tt = r >> 4; int bb = r & 15;
        out[(size_t)(bb * TLEN + tt) * DIM + nt0 * 128 + col] = v;
    )
}

__global__ __launch_bounds__(256) void gemm_score_kernel() {
    int id = blockIdx.x;                 // 0:(0,0) 1:(1,0) 2:(1,1)
    int ti = (id == 0) ? 0 : 1;
    int tj = (id == 2) ? 1 : 0;
    int g = blockIdx.y;
    const bf* Ah = g_Qh + (size_t)(g * GROWS + ti * 128) * DIM;
    const bf* Al = g_Ql + (size_t)(g * GROWS + ti * 128) * DIM;
    const bf* Bh = g_Kh + (size_t)(g * GROWS + tj * 128) * DIM;
    const bf* Bl = g_Kl + (size_t)(g * GROWS + tj * 128) * DIM;
    AccFrag acc[4][2];
    gemm_core(Ah, Al, DIM, Bh, Bl, DIM, DIM / 16, acc);
    bf* Sch = g_Sch + (size_t)g * GR2;
    bf* Scl = g_Scl + (size_t)g * GR2;
    EPILOGUE(
        int rr = ti * 128 + row;
        int ss = tj * 128 + col;
        float m = ((ss >> 4) <= (rr >> 4)) ? LRW * v : 0.0f;
        split1(Sch, Scl, (size_t)rr * GROWS + ss, m);
    )
}

__global__ __launch_bounds__(256) void gemm_av_kernel(float* __restrict__ out) {
    int ti = blockIdx.x;                 // 0..1 row tile within group
    int nt0 = blockIdx.y;                // 0..3
    int g = blockIdx.z;
    const bf* Ah = g_Sch + (size_t)g * GR2 + (size_t)ti * 128 * GROWS;
    const bf* Al = g_Scl + (size_t)g * GR2 + (size_t)ti * 128 * GROWS;
    const bf* Bh = g_Vth + (size_t)(nt0 * 128) * NROWS + g * GROWS;
    const bf* Bl = g_Vtl + (size_t)(nt0 * 128) * NROWS + g * GROWS;
    AccFrag acc[4][2];
    gemm_core(Ah, Al, GROWS, Bh, Bl, NROWS, 8 * (ti + 1), acc);
    EPILOGUE(
        int r = g * GROWS + ti * 128 + row;
        int tt = r >> 4; int bb = r & 15;
        size_t idx = (size_t)(bb * TLEN + tt) * DIM + nt0 * 128 + col;
        out[idx] += v;
    )
}

// ---------------------------------------------------------------------------
extern "C" void kernel_launch(void* const* d_in, const int* in_sizes, int n_in,
                              void* d_out, int out_size) {
    (void)in_sizes; (void)n_in; (void)out_size;
    const float* x  = (const float*)d_in[0];
    const float* Wq = (const float*)d_in[1];
    const float* Wk = (const float*)d_in[2];
    const float* Wv = (const float*)d_in[3];
    const float* m0 = (const float*)d_in[4];
    float* out = (float*)d_out;

    conv_x_kernel<<<32768, 256>>>(x);
    conv_w_kernel<<<768, 256>>>(Wq, Wk, Wv);
    gemm_qkv_kernel<<<dim3(512, 4, 3), 256>>>();
    transpose_kernel<<<dim3(1024, 8, 4), dim3(64, 8)>>>();
    gemm_u_kernel<<<dim3(4, 4, 256), 256>>>();
    scan_kernel<<<256, 256>>>(m0);
    gemm_score_kernel<<<dim3(3, 256), 256>>>();
    gemm_inter_kernel<<<dim3(512, 4), 256>>>(out);
    gemm_av_kernel<<<dim3(2, 4, 256), 256>>>(out);
}

// round 8
// speedup vs baseline: 1.7061x; 1.3768x over previous
#include <cuda_runtime.h>
#include <cuda_bf16.h>
#include <mma.h>
#include <cstdint>
#include <type_traits>

typedef __nv_bfloat16 bf;
typedef __nv_bfloat162 bf2;
namespace wm = nvcuda::wmma;
using AccFrag = wm::fragment<wm::accumulator, 16, 16, 16, float>;

#define BATCH 16
#define TLEN  4096
#define DIM   512
#define NROWS 65536              // time-major rows r = t*16 + b
#define GROWS 256                // rows per group (16 t-steps x 16 batch)
#define NG    256
#define DD2   (DIM*DIM)          // 262144
#define GR2   (GROWS*GROWS)
#define LRW   0.01f

// ---------------- device scratch ----------------
__device__ __align__(256) bf g_Xh[(size_t)NROWS*DIM];
__device__ __align__(256) bf g_Xl[(size_t)NROWS*DIM];
__device__ __align__(256) bf g_Wh[3*DD2];
__device__ __align__(256) bf g_Wl[3*DD2];
__device__ __align__(256) bf g_Qh[(size_t)NROWS*DIM];
__device__ __align__(256) bf g_Ql[(size_t)NROWS*DIM];
__device__ __align__(256) bf g_Kh[(size_t)NROWS*DIM];
__device__ __align__(256) bf g_Kl[(size_t)NROWS*DIM];
__device__ __align__(256) bf g_Vh[(size_t)NROWS*DIM];
__device__ __align__(256) bf g_Vl[(size_t)NROWS*DIM];
__device__ __align__(256) float g_U[(size_t)NG*DD2];
__device__ __align__(256) bf g_Sh[(size_t)NG*DD2];
__device__ __align__(256) bf g_Sl[(size_t)NG*DD2];
__device__ __align__(256) bf g_Sch[(size_t)NG*GR2];
__device__ __align__(256) bf g_Scl[(size_t)NG*GR2];

// ---------------------------------------------------------------------------
// 128x128 GEMM core, wmma bf16 hi/lo FUSED 3-product (Ah*Bh + Al*Bh + Ah*Bl),
// BK=16, single smem buffer + register prefetch of next chunk.
//   AT=false: A stored [m][k] k-contig (row_major frag)
//   AT=true : A stored [k][m] m-contig (col_major frag)  -- "transposed" read
//   BT=false: B stored [n][k] k-contig (col_major frag)  -- NT
//   BT=true : B stored [k][n] n-contig (row_major frag)  -- NN
// 256 threads, 8 warps in 2x4, warp tile 64x32 = 4x2 fragments.
// ---------------------------------------------------------------------------
template <bool AT, bool BT>
__device__ __forceinline__ void gemm_core(
    const bf* __restrict__ Ah, const bf* __restrict__ Al, size_t lda,
    const bf* __restrict__ Bh, const bf* __restrict__ Bl, size_t ldb,
    int nktp, AccFrag acc[4][2])
{
    constexpr int ALD = AT ? 136 : 24;
    constexpr int BLD = BT ? 136 : 24;
    __shared__ bf Ash[AT ? 16 * 136 : 128 * 24];
    __shared__ bf Asl[AT ? 16 * 136 : 128 * 24];
    __shared__ bf Bsh[BT ? 16 * 136 : 128 * 24];
    __shared__ bf Bsl[BT ? 16 * 136 : 128 * 24];

    const int tid = threadIdx.x;
    const int w   = tid >> 5;
    const int wmi = w >> 2, wni = w & 3;

    const int arow = AT ? (tid >> 4) : (tid >> 1);
    const int achk = AT ? (tid & 15) : (tid & 1);
    const int brow = BT ? (tid >> 4) : (tid >> 1);
    const int bchk = BT ? (tid & 15) : (tid & 1);
    const int a_soff = arow * ALD + achk * 8;
    const int b_soff = brow * BLD + bchk * 8;

    auto a_goff = [&](int kt) -> size_t {
        return AT ? (size_t)(kt * 16 + arow) * lda + achk * 8
                  : (size_t)arow * lda + kt * 16 + achk * 8;
    };
    auto b_goff = [&](int kt) -> size_t {
        return BT ? (size_t)(kt * 16 + brow) * ldb + bchk * 8
                  : (size_t)brow * ldb + kt * 16 + bchk * 8;
    };

#pragma unroll
    for (int mt = 0; mt < 4; mt++)
#pragma unroll
        for (int n2 = 0; n2 < 2; n2++)
            wm::fill_fragment(acc[mt][n2], 0.0f);

    using ALay = typename std::conditional<AT, wm::col_major, wm::row_major>::type;
    using BLay = typename std::conditional<BT, wm::row_major, wm::col_major>::type;

    // prefetch chunk 0
    size_t ao = a_goff(0), bo = b_goff(0);
    uint4 avh = *(const uint4*)(Ah + ao);
    uint4 avl = *(const uint4*)(Al + ao);
    uint4 bvh = *(const uint4*)(Bh + bo);
    uint4 bvl = *(const uint4*)(Bl + bo);

    for (int kt = 0; kt < nktp; ++kt) {
        __syncthreads();   // previous chunk fully consumed
        *(uint4*)(&Ash[a_soff]) = avh;
        *(uint4*)(&Asl[a_soff]) = avl;
        *(uint4*)(&Bsh[b_soff]) = bvh;
        *(uint4*)(&Bsl[b_soff]) = bvl;
        __syncthreads();

        if (kt + 1 < nktp) {   // prefetch next chunk; latency hides under MMAs
            ao = a_goff(kt + 1); bo = b_goff(kt + 1);
            avh = *(const uint4*)(Ah + ao);
            avl = *(const uint4*)(Al + ao);
            bvh = *(const uint4*)(Bh + bo);
            bvl = *(const uint4*)(Bl + bo);
        }

        wm::fragment<wm::matrix_a, 16, 16, 16, bf, ALay> afh[4], afl[4];
        wm::fragment<wm::matrix_b, 16, 16, 16, bf, BLay> bfh[2], bfl[2];
#pragma unroll
        for (int mt = 0; mt < 4; mt++) {
            int m0 = wmi * 64 + mt * 16;
            int off = AT ? m0 : m0 * ALD;
            wm::load_matrix_sync(afh[mt], &Ash[off], ALD);
            wm::load_matrix_sync(afl[mt], &Asl[off], ALD);
        }
#pragma unroll
        for (int n2 = 0; n2 < 2; n2++) {
            int n0 = wni * 32 + n2 * 16;
            int off = BT ? n0 : n0 * BLD;
            wm::load_matrix_sync(bfh[n2], &Bsh[off], BLD);
            wm::load_matrix_sync(bfl[n2], &Bsl[off], BLD);
        }
#pragma unroll
        for (int mt = 0; mt < 4; mt++)
#pragma unroll
            for (int n2 = 0; n2 < 2; n2++) {
                wm::mma_sync(acc[mt][n2], afh[mt], bfh[n2], acc[mt][n2]);
                wm::mma_sync(acc[mt][n2], afl[mt], bfh[n2], acc[mt][n2]);
                wm::mma_sync(acc[mt][n2], afh[mt], bfl[n2], acc[mt][n2]);
            }
    }
    __syncthreads();
}

__device__ __forceinline__ float* warp_stage() {
    __shared__ float st[8][320];      // per-warp 16x20 staging
    return st[threadIdx.x >> 5];
}

// Epilogue: stage each frag through smem, then scalar writes.
// Exposes: row (0..127 tile-local), col (0..127 tile-local), v (float).
#define EPILOGUE(...)                                                     \
  { float* stg = warp_stage();                                            \
    const int lane = threadIdx.x & 31;                                    \
    const int w = threadIdx.x >> 5, wm_ = w >> 2, wn_ = w & 3;            \
    for (int mt = 0; mt < 4; mt++)                                        \
      for (int n2 = 0; n2 < 2; n2++) {                                    \
        wm::store_matrix_sync(stg, acc[mt][n2], 20, wm::mem_row_major);   \
        __syncwarp();                                                     \
        _Pragma("unroll")                                                 \
        for (int e = 0; e < 8; e++) {                                     \
          int lr = 2 * e + (lane >> 4); int lc = lane & 15;               \
          int row = wm_ * 64 + mt * 16 + lr;                              \
          int col = wn_ * 32 + n2 * 16 + lc;                              \
          float v = stg[lr * 20 + lc];                                    \
          __VA_ARGS__                                                     \
        }                                                                 \
        __syncwarp();                                                     \
      } }

__device__ __forceinline__ void split1(bf* Oh, bf* Ol, size_t idx, float v) {
    bf h = __float2bfloat16(v);
    Oh[idx] = h;
    Ol[idx] = __float2bfloat16(v - __bfloat162float(h));
}
__device__ __forceinline__ void split_store(bf* Oh, bf* Ol, size_t idx,
                                            float v0, float v1) {
    bf h0 = __float2bfloat16(v0), h1 = __float2bfloat16(v1);
    bf2 ph; ph.x = h0; ph.y = h1;
    bf2 pl; pl.x = __float2bfloat16(v0 - __bfloat162float(h0));
            pl.y = __float2bfloat16(v1 - __bfloat162float(h1));
    *(bf2*)(Oh + idx) = ph;
    *(bf2*)(Ol + idx) = pl;
}

// ---------------- conversion / scan ----------------------------------------
__global__ void conv_x_kernel(const float* __restrict__ x) {
    int i = blockIdx.x * 256 + threadIdx.x;       // over NROWS*DIM/4
    int r = i >> 7;
    int d = (i & 127) * 4;
    int tt = r >> 4, bb = r & 15;
    float4 v = *(const float4*)(x + (size_t)(bb * TLEN + tt) * DIM + d);
    size_t o = (size_t)r * DIM + d;
    split_store(g_Xh, g_Xl, o,     v.x, v.y);
    split_store(g_Xh, g_Xl, o + 2, v.z, v.w);
}

__global__ void conv_w_kernel(const float* __restrict__ Wq,
                              const float* __restrict__ Wk,
                              const float* __restrict__ Wv) {
    int i = blockIdx.x * 256 + threadIdx.x;       // over 3*DD2/4
    int z = i >> 16;
    int off = (i & 65535) * 4;
    const float* src = (z == 0) ? Wq : (z == 1) ? Wk : Wv;
    float4 v = *(const float4*)(src + off);
    size_t o = (size_t)z * DD2 + off;
    split_store(g_Wh, g_Wl, o,     v.x, v.y);
    split_store(g_Wh, g_Wl, o + 2, v.z, v.w);
}

__global__ void scan_kernel(const float* __restrict__ mem0) {
    int i4 = (blockIdx.x * 256 + threadIdx.x) * 4;    // over DD2
    float4 acc = *(const float4*)(mem0 + i4);
    for (int g = 0; g < NG; g++) {
        size_t off = (size_t)g * DD2 + i4;
        float4 u = *(const float4*)(g_U + off);
        split_store(g_Sh, g_Sl, off,     acc.x, acc.y);
        split_store(g_Sh, g_Sl, off + 2, acc.z, acc.w);
        acc.x = fmaf(LRW, u.x, acc.x);
        acc.y = fmaf(LRW, u.y, acc.y);
        acc.z = fmaf(LRW, u.z, acc.z);
        acc.w = fmaf(LRW, u.w, acc.w);
    }
}

// ---------------- GEMM kernels ---------------------------------------------
__global__ __launch_bounds__(256) void gemm_qkv_kernel() {
    int mt0 = blockIdx.x, nt0 = blockIdx.y, z = blockIdx.z;
    const bf* Ah = g_Xh + (size_t)mt0 * 128 * DIM;
    const bf* Al = g_Xl + (size_t)mt0 * 128 * DIM;
    const bf* Bh = g_Wh + (size_t)z * DD2 + (size_t)nt0 * 128 * DIM;
    const bf* Bl = g_Wl + (size_t)z * DD2 + (size_t)nt0 * 128 * DIM;
    AccFrag acc[4][2];
    gemm_core<false, false>(Ah, Al, DIM, Bh, Bl, DIM, DIM / 16, acc);
    bf* Oh = (z == 0) ? g_Qh : (z == 1) ? g_Kh : g_Vh;
    bf* Ol = (z == 0) ? g_Ql : (z == 1) ? g_Kl : g_Vl;
    EPILOGUE(
        size_t idx = (size_t)(mt0 * 128 + row) * DIM + nt0 * 128 + col;
        split1(Oh, Ol, idx, v);
    )
}

// U_g[d,e] = sum_r V[r,d] K[r,e]   -- A = V read transposed, B = K read NN
__global__ __launch_bounds__(256) void gemm_u_kernel() {
    int d0 = blockIdx.x * 128, e0 = blockIdx.y * 128, g = blockIdx.z;
    const bf* Ah = g_Vh + (size_t)(g * GROWS) * DIM + d0;
    const bf* Al = g_Vl + (size_t)(g * GROWS) * DIM + d0;
    const bf* Bh = g_Kh + (size_t)(g * GROWS) * DIM + e0;
    const bf* Bl = g_Kl + (size_t)(g * GROWS) * DIM + e0;
    AccFrag acc[4][2];
    gemm_core<true, true>(Ah, Al, DIM, Bh, Bl, DIM, GROWS / 16, acc);
    float* U = g_U + (size_t)g * DD2;
    EPILOGUE(
        U[(size_t)(d0 + row) * DIM + e0 + col] = v;
    )
}

__global__ __launch_bounds__(256) void gemm_inter_kernel(float* __restrict__ out) {
    int mt0 = blockIdx.x, nt0 = blockIdx.y;
    int g = mt0 >> 1;
    const bf* Ah = g_Qh + (size_t)mt0 * 128 * DIM;
    const bf* Al = g_Ql + (size_t)mt0 * 128 * DIM;
    const bf* Bh = g_Sh + (size_t)g * DD2 + (size_t)nt0 * 128 * DIM;
    const bf* Bl = g_Sl + (size_t)g * DD2 + (size_t)nt0 * 128 * DIM;
    AccFrag acc[4][2];
    gemm_core<false, false>(Ah, Al, DIM, Bh, Bl, DIM, DIM / 16, acc);
    EPILOGUE(
        int r = mt0 * 128 + row;
        int tt = r >> 4; int bb = r & 15;
        out[(size_t)(bb * TLEN + tt) * DIM + nt0 * 128 + col] = v;
    )
}

__global__ __launch_bounds__(256) void gemm_score_kernel() {
    int id = blockIdx.x;                 // 0:(0,0) 1:(1,0) 2:(1,1)
    int ti = (id == 0) ? 0 : 1;
    int tj = (id == 2) ? 1 : 0;
    int g = blockIdx.y;
    const bf* Ah = g_Qh + (size_t)(g * GROWS + ti * 128) * DIM;
    const bf* Al = g_Ql + (size_t)(g * GROWS + ti * 128) * DIM;
    const bf* Bh = g_Kh + (size_t)(g * GROWS + tj * 128) * DIM;
    const bf* Bl = g_Kl + (size_t)(g * GROWS + tj * 128) * DIM;
    AccFrag acc[4][2];
    gemm_core<false, false>(Ah, Al, DIM, Bh, Bl, DIM, DIM / 16, acc);
    bf* Sch = g_Sch + (size_t)g * GR2;
    bf* Scl = g_Scl + (size_t)g * GR2;
    EPILOGUE(
        int rr = ti * 128 + row;
        int ss = tj * 128 + col;
        float m = ((ss >> 4) <= (rr >> 4)) ? LRW * v : 0.0f;
        split1(Sch, Scl, (size_t)rr * GROWS + ss, m);
    )
}

// out[r,d] += sum_s Sc[r,s] V[s,d]  -- B = V read NN
__global__ __launch_bounds__(256) void gemm_av_kernel(float* __restrict__ out) {
    int ti = blockIdx.x;                 // 0..1 row tile within group
    int nt0 = blockIdx.y;                // 0..3
    int g = blockIdx.z;
    const bf* Ah = g_Sch + (size_t)g * GR2 + (size_t)ti * 128 * GROWS;
    const bf* Al = g_Scl + (size_t)g * GR2 + (size_t)ti * 128 * GROWS;
    const bf* Bh = g_Vh + (size_t)(g * GROWS) * DIM + nt0 * 128;
    const bf* Bl = g_Vl + (size_t)(g * GROWS) * DIM + nt0 * 128;
    AccFrag acc[4][2];
    gemm_core<false, true>(Ah, Al, GROWS, Bh, Bl, DIM, 8 * (ti + 1), acc);
    EPILOGUE(
        int r = g * GROWS + ti * 128 + row;
        int tt = r >> 4; int bb = r & 15;
        size_t idx = (size_t)(bb * TLEN + tt) * DIM + nt0 * 128 + col;
        out[idx] += v;
    )
}

// ---------------------------------------------------------------------------
extern "C" void kernel_launch(void* const* d_in, const int* in_sizes, int n_in,
                              void* d_out, int out_size) {
    (void)in_sizes; (void)n_in; (void)out_size;
    const float* x  = (const float*)d_in[0];
    const float* Wq = (const float*)d_in[1];
    const float* Wk = (const float*)d_in[2];
    const float* Wv = (const float*)d_in[3];
    const float* m0 = (const float*)d_in[4];
    float* out = (float*)d_out;

    conv_x_kernel<<<32768, 256>>>(x);
    conv_w_kernel<<<768, 256>>>(Wq, Wk, Wv);
    gemm_qkv_kernel<<<dim3(512, 4, 3), 256>>>();
    gemm_u_kernel<<<dim3(4, 4, 256), 256>>>();
    scan_kernel<<<256, 256>>>(m0);
    gemm_score_kernel<<<dim3(3, 256), 256>>>();
    gemm_inter_kernel<<<dim3(512, 4), 256>>>(out);
    gemm_av_kernel<<<dim3(2, 4, 256), 256>>>(out);
}

// round 9
// speedup vs baseline: 1.7839x; 1.0456x over previous
#include <cuda_runtime.h>
#include <cuda_bf16.h>
#include <mma.h>
#include <cstdint>
#include <type_traits>

typedef __nv_bfloat16 bf;
typedef __nv_bfloat162 bf2;
namespace wm = nvcuda::wmma;
using AccFrag = wm::fragment<wm::accumulator, 16, 16, 16, float>;

#define BATCH 16
#define TLEN  4096
#define DIM   512
#define NROWS 65536              // time-major rows r = t*16 + b
#define GROWS 256                // rows per group (16 t-steps x 16 batch)
#define NG    256
#define DD2   (DIM*DIM)          // 262144
#define GR2   (GROWS*GROWS)
#define LRW   0.01f

// ---------------- device scratch ----------------
__device__ __align__(256) bf g_Xh[(size_t)NROWS*DIM];
__device__ __align__(256) bf g_Xl[(size_t)NROWS*DIM];
__device__ __align__(256) bf g_Wh[3*DD2];
__device__ __align__(256) bf g_Wl[3*DD2];
__device__ __align__(256) bf g_Qh[(size_t)NROWS*DIM];
__device__ __align__(256) bf g_Ql[(size_t)NROWS*DIM];
__device__ __align__(256) bf g_Kh[(size_t)NROWS*DIM];
__device__ __align__(256) bf g_Kl[(size_t)NROWS*DIM];
__device__ __align__(256) bf g_Vh[(size_t)NROWS*DIM];
__device__ __align__(256) bf g_Vl[(size_t)NROWS*DIM];
__device__ __align__(256) float g_U[(size_t)NG*DD2];
__device__ __align__(256) bf g_Sh[(size_t)NG*DD2];
__device__ __align__(256) bf g_Sl[(size_t)NG*DD2];
__device__ __align__(256) bf g_Sch[(size_t)NG*GR2];
__device__ __align__(256) bf g_Scl[(size_t)NG*GR2];

#define POOL_BYTES 40960   // 4 x 10KB tile arrays; epilogue staging aliases it

// ---------------------------------------------------------------------------
// 128x128 GEMM core, wmma bf16 hi/lo fused 3-product, BK=32,
// single smem buffer + register prefetch of next chunk.
//   AT=false: A stored [m][k] k-contig (row_major frag)
//   AT=true : A stored [k][m] m-contig (col_major frag)
//   BT=false: B stored [n][k] k-contig (col_major frag)  -- NT
//   BT=true : B stored [k][n] n-contig (row_major frag)  -- NN
// 256 threads, 8 warps 2x4, warp tile 64x32 = 4x2 fragments.
// ---------------------------------------------------------------------------
template <bool AT, bool BT>
__device__ __forceinline__ void gemm_core(char* smpool,
    const bf* __restrict__ Ah, const bf* __restrict__ Al, size_t lda,
    const bf* __restrict__ Bh, const bf* __restrict__ Bl, size_t ldb,
    int nktp, AccFrag acc[4][2])
{
    constexpr int ALD = AT ? 136 : 40;   // AT tile: 32x136, else 128x40
    constexpr int BLD = BT ? 136 : 40;
    bf* Ash = (bf*)(smpool);
    bf* Asl = (bf*)(smpool + 10240);
    bf* Bsh = (bf*)(smpool + 20480);
    bf* Bsl = (bf*)(smpool + 30720);

    const int tid = threadIdx.x;
    const int w   = tid >> 5;
    const int wmi = w >> 2, wni = w & 3;

    // loader: each thread moves 2x uint4 (16 bf) per array per chunk
    const int ar = AT ? (tid >> 3) : (tid >> 1);
    const int ac = (AT ? (tid & 7) : (tid & 1)) * 2;   // 8-elem chunk base
    const int br = BT ? (tid >> 3) : (tid >> 1);
    const int bc = (BT ? (tid & 7) : (tid & 1)) * 2;
    const int aso = ar * ALD + ac * 8;
    const int bso = br * BLD + bc * 8;

    auto agof = [&](int kt, int j) -> size_t {
        return AT ? (size_t)(kt * 32 + ar) * lda + (ac + j) * 8
                  : (size_t)ar * lda + kt * 32 + (ac + j) * 8;
    };
    auto bgof = [&](int kt, int j) -> size_t {
        return BT ? (size_t)(kt * 32 + br) * ldb + (bc + j) * 8
                  : (size_t)br * ldb + kt * 32 + (bc + j) * 8;
    };

#pragma unroll
    for (int mt = 0; mt < 4; mt++)
#pragma unroll
        for (int n2 = 0; n2 < 2; n2++)
            wm::fill_fragment(acc[mt][n2], 0.0f);

    using ALay = typename std::conditional<AT, wm::col_major, wm::row_major>::type;
    using BLay = typename std::conditional<BT, wm::row_major, wm::col_major>::type;

    uint4 avh[2], avl[2], bvh[2], bvl[2];
#pragma unroll
    for (int j = 0; j < 2; j++) {
        avh[j] = *(const uint4*)(Ah + agof(0, j));
        avl[j] = *(const uint4*)(Al + agof(0, j));
        bvh[j] = *(const uint4*)(Bh + bgof(0, j));
        bvl[j] = *(const uint4*)(Bl + bgof(0, j));
    }

    for (int kt = 0; kt < nktp; ++kt) {
        __syncthreads();   // previous chunk fully consumed
#pragma unroll
        for (int j = 0; j < 2; j++) {
            *(uint4*)(&Ash[aso + j * 8]) = avh[j];
            *(uint4*)(&Asl[aso + j * 8]) = avl[j];
            *(uint4*)(&Bsh[bso + j * 8]) = bvh[j];
            *(uint4*)(&Bsl[bso + j * 8]) = bvl[j];
        }
        __syncthreads();

        if (kt + 1 < nktp) {   // prefetch next chunk; latency hides under MMAs
#pragma unroll
            for (int j = 0; j < 2; j++) {
                avh[j] = *(const uint4*)(Ah + agof(kt + 1, j));
                avl[j] = *(const uint4*)(Al + agof(kt + 1, j));
                bvh[j] = *(const uint4*)(Bh + bgof(kt + 1, j));
                bvl[j] = *(const uint4*)(Bl + bgof(kt + 1, j));
            }
        }

#pragma unroll
        for (int kk = 0; kk < 2; kk++) {
            wm::fragment<wm::matrix_a, 16, 16, 16, bf, ALay> afh[4], afl[4];
            wm::fragment<wm::matrix_b, 16, 16, 16, bf, BLay> bfh[2], bfl[2];
#pragma unroll
            for (int mt = 0; mt < 4; mt++) {
                int m0 = wmi * 64 + mt * 16;
                int off = AT ? (kk * 16 * ALD + m0) : (m0 * ALD + kk * 16);
                wm::load_matrix_sync(afh[mt], &Ash[off], ALD);
                wm::load_matrix_sync(afl[mt], &Asl[off], ALD);
            }
#pragma unroll
            for (int n2 = 0; n2 < 2; n2++) {
                int n0 = wni * 32 + n2 * 16;
                int off = BT ? (kk * 16 * BLD + n0) : (n0 * BLD + kk * 16);
                wm::load_matrix_sync(bfh[n2], &Bsh[off], BLD);
                wm::load_matrix_sync(bfl[n2], &Bsl[off], BLD);
            }
#pragma unroll
            for (int mt = 0; mt < 4; mt++)
#pragma unroll
                for (int n2 = 0; n2 < 2; n2++) {
                    wm::mma_sync(acc[mt][n2], afh[mt], bfh[n2], acc[mt][n2]);
                    wm::mma_sync(acc[mt][n2], afl[mt], bfh[n2], acc[mt][n2]);
                    wm::mma_sync(acc[mt][n2], afh[mt], bfl[n2], acc[mt][n2]);
                }
        }
    }
    __syncthreads();   // protect pool before epilogue aliases it
}

// Epilogue: stage each frag through smem (aliases pool), then scalar writes.
// Exposes: row (0..127 tile-local), col (0..127 tile-local), v (float).
#define EPILOGUE(...)                                                     \
  { float* stg = (float*)(smpool) + (threadIdx.x >> 5) * 320;             \
    const int lane = threadIdx.x & 31;                                    \
    const int w = threadIdx.x >> 5, wm_ = w >> 2, wn_ = w & 3;            \
    for (int mt = 0; mt < 4; mt++)                                        \
      for (int n2 = 0; n2 < 2; n2++) {                                    \
        wm::store_matrix_sync(stg, acc[mt][n2], 20, wm::mem_row_major);   \
        __syncwarp();                                                     \
        _Pragma("unroll")                                                 \
        for (int e = 0; e < 8; e++) {                                     \
          int lr = 2 * e + (lane >> 4); int lc = lane & 15;               \
          int row = wm_ * 64 + mt * 16 + lr;                              \
          int col = wn_ * 32 + n2 * 16 + lc;                              \
          float v = stg[lr * 20 + lc];                                    \
          __VA_ARGS__                                                     \
        }                                                                 \
        __syncwarp();                                                     \
      } }

#define DECL_POOL __shared__ __align__(16) char smpool[POOL_BYTES]

__device__ __forceinline__ void split1(bf* Oh, bf* Ol, size_t idx, float v) {
    bf h = __float2bfloat16(v);
    Oh[idx] = h;
    Ol[idx] = __float2bfloat16(v - __bfloat162float(h));
}
__device__ __forceinline__ void split_store(bf* Oh, bf* Ol, size_t idx,
                                            float v0, float v1) {
    bf h0 = __float2bfloat16(v0), h1 = __float2bfloat16(v1);
    bf2 ph; ph.x = h0; ph.y = h1;
    bf2 pl; pl.x = __float2bfloat16(v0 - __bfloat162float(h0));
            pl.y = __float2bfloat16(v1 - __bfloat162float(h1));
    *(bf2*)(Oh + idx) = ph;
    *(bf2*)(Ol + idx) = pl;
}

// ---------------- conversion / scan ----------------------------------------
__global__ void conv_x_kernel(const float* __restrict__ x) {
    int i = blockIdx.x * 256 + threadIdx.x;       // over NROWS*DIM/4
    int r = i >> 7;
    int d = (i & 127) * 4;
    int tt = r >> 4, bb = r & 15;
    float4 v = *(const float4*)(x + (size_t)(bb * TLEN + tt) * DIM + d);
    size_t o = (size_t)r * DIM + d;
    split_store(g_Xh, g_Xl, o,     v.x, v.y);
    split_store(g_Xh, g_Xl, o + 2, v.z, v.w);
}

__global__ void conv_w_kernel(const float* __restrict__ Wq,
                              const float* __restrict__ Wk,
                              const float* __restrict__ Wv) {
    int i = blockIdx.x * 256 + threadIdx.x;       // over 3*DD2/4
    int z = i >> 16;
    int off = (i & 65535) * 4;
    const float* src = (z == 0) ? Wq : (z == 1) ? Wk : Wv;
    float4 v = *(const float4*)(src + off);
    size_t o = (size_t)z * DD2 + off;
    split_store(g_Wh, g_Wl, o,     v.x, v.y);
    split_store(g_Wh, g_Wl, o + 2, v.z, v.w);
}

__global__ void scan_kernel(const float* __restrict__ mem0) {
    int i4 = (blockIdx.x * 256 + threadIdx.x) * 4;    // over DD2
    float4 acc = *(const float4*)(mem0 + i4);
    for (int g = 0; g < NG; g++) {
        size_t off = (size_t)g * DD2 + i4;
        float4 u = *(const float4*)(g_U + off);
        split_store(g_Sh, g_Sl, off,     acc.x, acc.y);
        split_store(g_Sh, g_Sl, off + 2, acc.z, acc.w);
        acc.x = fmaf(LRW, u.x, acc.x);
        acc.y = fmaf(LRW, u.y, acc.y);
        acc.z = fmaf(LRW, u.z, acc.z);
        acc.w = fmaf(LRW, u.w, acc.w);
    }
}

// ---------------- GEMM kernels ---------------------------------------------
__global__ __launch_bounds__(256) void gemm_qkv_kernel() {
    DECL_POOL;
    int mt0 = blockIdx.x, nt0 = blockIdx.y, z = blockIdx.z;
    const bf* Ah = g_Xh + (size_t)mt0 * 128 * DIM;
    const bf* Al = g_Xl + (size_t)mt0 * 128 * DIM;
    const bf* Bh = g_Wh + (size_t)z * DD2 + (size_t)nt0 * 128 * DIM;
    const bf* Bl = g_Wl + (size_t)z * DD2 + (size_t)nt0 * 128 * DIM;
    AccFrag acc[4][2];
    gemm_core<false, false>(smpool, Ah, Al, DIM, Bh, Bl, DIM, DIM / 32, acc);
    bf* Oh = (z == 0) ? g_Qh : (z == 1) ? g_Kh : g_Vh;
    bf* Ol = (z == 0) ? g_Ql : (z == 1) ? g_Kl : g_Vl;
    EPILOGUE(
        size_t idx = (size_t)(mt0 * 128 + row) * DIM + nt0 * 128 + col;
        split1(Oh, Ol, idx, v);
    )
}

// U_g[d,e] = sum_r V[r,d] K[r,e]   -- A = V read transposed, B = K read NN
__global__ __launch_bounds__(256) void gemm_u_kernel() {
    DECL_POOL;
    int d0 = blockIdx.x * 128, e0 = blockIdx.y * 128, g = blockIdx.z;
    const bf* Ah = g_Vh + (size_t)(g * GROWS) * DIM + d0;
    const bf* Al = g_Vl + (size_t)(g * GROWS) * DIM + d0;
    const bf* Bh = g_Kh + (size_t)(g * GROWS) * DIM + e0;
    const bf* Bl = g_Kl + (size_t)(g * GROWS) * DIM + e0;
    AccFrag acc[4][2];
    gemm_core<true, true>(smpool, Ah, Al, DIM, Bh, Bl, DIM, GROWS / 32, acc);
    float* U = g_U + (size_t)g * DD2;
    EPILOGUE(
        U[(size_t)(d0 + row) * DIM + e0 + col] = v;
    )
}

__global__ __launch_bounds__(256) void gemm_inter_kernel(float* __restrict__ out) {
    DECL_POOL;
    int mt0 = blockIdx.x, nt0 = blockIdx.y;
    int g = mt0 >> 1;
    const bf* Ah = g_Qh + (size_t)mt0 * 128 * DIM;
    const bf* Al = g_Ql + (size_t)mt0 * 128 * DIM;
    const bf* Bh = g_Sh + (size_t)g * DD2 + (size_t)nt0 * 128 * DIM;
    const bf* Bl = g_Sl + (size_t)g * DD2 + (size_t)nt0 * 128 * DIM;
    AccFrag acc[4][2];
    gemm_core<false, false>(smpool, Ah, Al, DIM, Bh, Bl, DIM, DIM / 32, acc);
    EPILOGUE(
        int r = mt0 * 128 + row;
        int tt = r >> 4; int bb = r & 15;
        out[(size_t)(bb * TLEN + tt) * DIM + nt0 * 128 + col] = v;
    )
}

__global__ __launch_bounds__(256) void gemm_score_kernel() {
    DECL_POOL;
    int id = blockIdx.x;                 // 0:(0,0) 1:(1,0) 2:(1,1)
    int ti = (id == 0) ? 0 : 1;
    int tj = (id == 2) ? 1 : 0;
    int g = blockIdx.y;
    const bf* Ah = g_Qh + (size_t)(g * GROWS + ti * 128) * DIM;
    const bf* Al = g_Ql + (size_t)(g * GROWS + ti * 128) * DIM;
    const bf* Bh = g_Kh + (size_t)(g * GROWS + tj * 128) * DIM;
    const bf* Bl = g_Kl + (size_t)(g * GROWS + tj * 128) * DIM;
    AccFrag acc[4][2];
    gemm_core<false, false>(smpool, Ah, Al, DIM, Bh, Bl, DIM, DIM / 32, acc);
    bf* Sch = g_Sch + (size_t)g * GR2;
    bf* Scl = g_Scl + (size_t)g * GR2;
    EPILOGUE(
        int rr = ti * 128 + row;
        int ss = tj * 128 + col;
        float m = ((ss >> 4) <= (rr >> 4)) ? LRW * v : 0.0f;
        split1(Sch, Scl, (size_t)rr * GROWS + ss, m);
    )
}

// out[r,d] += sum_s Sc[r,s] V[s,d]  -- B = V read NN
__global__ __launch_bounds__(256) void gemm_av_kernel(float* __restrict__ out) {
    DECL_POOL;
    int ti = blockIdx.x;                 // 0..1 row tile within group
    int nt0 = blockIdx.y;                // 0..3
    int g = blockIdx.z;
    const bf* Ah = g_Sch + (size_t)g * GR2 + (size_t)ti * 128 * GROWS;
    const bf* Al = g_Scl + (size_t)g * GR2 + (size_t)ti * 128 * GROWS;
    const bf* Bh = g_Vh + (size_t)(g * GROWS) * DIM + nt0 * 128;
    const bf* Bl = g_Vl + (size_t)(g * GROWS) * DIM + nt0 * 128;
    AccFrag acc[4][2];
    gemm_core<false, true>(smpool, Ah, Al, GROWS, Bh, Bl, DIM, 4 * (ti + 1), acc);
    EPILOGUE(
        int r = g * GROWS + ti * 128 + row;
        int tt = r >> 4; int bb = r & 15;
        size_t idx = (size_t)(bb * TLEN + tt) * DIM + nt0 * 128 + col;
        out[idx] += v;
    )
}

// ---------------------------------------------------------------------------
extern "C" void kernel_launch(void* const* d_in, const int* in_sizes, int n_in,
                              void* d_out, int out_size) {
    (void)in_sizes; (void)n_in; (void)out_size;
    const float* x  = (const float*)d_in[0];
    const float* Wq = (const float*)d_in[1];
    const float* Wk = (const float*)d_in[2];
    const float* Wv = (const float*)d_in[3];
    const float* m0 = (const float*)d_in[4];
    float* out = (float*)d_out;

    conv_x_kernel<<<32768, 256>>>(x);
    conv_w_kernel<<<768, 256>>>(Wq, Wk, Wv);
    gemm_qkv_kernel<<<dim3(512, 4, 3), 256>>>();
    gemm_u_kernel<<<dim3(4, 4, 256), 256>>>();
    scan_kernel<<<256, 256>>>(m0);
    gemm_score_kernel<<<dim3(3, 256), 256>>>();
    gemm_inter_kernel<<<dim3(512, 4), 256>>>(out);
    gemm_av_kernel<<<dim3(2, 4, 256), 256>>>(out);
}

// round 10
// speedup vs baseline: 1.9609x; 1.0992x over previous
#include <cuda_runtime.h>
#include <cuda_bf16.h>
#include <mma.h>
#include <cstdint>
#include <type_traits>

typedef __nv_bfloat16 bf;
typedef __nv_bfloat162 bf2;
namespace wm = nvcuda::wmma;
using AccFrag = wm::fragment<wm::accumulator, 16, 16, 16, float>;

#define BATCH 16
#define TLEN  4096
#define DIM   512
#define NROWS 65536              // time-major rows r = t*16 + b
#define GROWS 256                // rows per group (16 t-steps x 16 batch)
#define NG    256
#define DD2   (DIM*DIM)          // 262144
#define GR2   (GROWS*GROWS)
#define LRW   0.01f

// ---------------- device scratch ----------------
__device__ __align__(256) bf g_Xh[(size_t)NROWS*DIM];
__device__ __align__(256) bf g_Xl[(size_t)NROWS*DIM];
__device__ __align__(256) bf g_Wh[3*DD2];
__device__ __align__(256) bf g_Wl[3*DD2];
__device__ __align__(256) bf g_Qh[(size_t)NROWS*DIM];
__device__ __align__(256) bf g_Ql[(size_t)NROWS*DIM];
__device__ __align__(256) bf g_Kh[(size_t)NROWS*DIM];
__device__ __align__(256) bf g_Kl[(size_t)NROWS*DIM];
__device__ __align__(256) bf g_Vh[(size_t)NROWS*DIM];
__device__ __align__(256) bf g_Vl[(size_t)NROWS*DIM];
__device__ __align__(256) float g_U[(size_t)NG*DD2];
__device__ __align__(256) bf g_Sh[(size_t)NG*DD2];
__device__ __align__(256) bf g_Sl[(size_t)NG*DD2];
__device__ __align__(256) bf g_Sch[(size_t)NG*GR2];
__device__ __align__(256) bf g_Scl[(size_t)NG*GR2];

#define POOL_BYTES 40960   // 4 x 10KB tile arrays; epilogue staging aliases it

// ---------------------------------------------------------------------------
// 128x128 GEMM core, wmma bf16 hi/lo fused 3-product, BK=32, single buffer,
// NO register prefetch (occupancy-overlap instead: 2 CTAs/SM).
//   AT=false: A stored [m][k] k-contig (row_major frag)
//   AT=true : A stored [k][m] m-contig (col_major frag)
//   BT=false: B stored [n][k] k-contig (col_major frag)  -- NT
//   BT=true : B stored [k][n] n-contig (row_major frag)  -- NN
// 256 threads, 8 warps 2x4, warp tile 64x32 = 4x2 fragments.
// ---------------------------------------------------------------------------
template <bool AT, bool BT>
__device__ __forceinline__ void gemm_core(char* smpool,
    const bf* __restrict__ Ah, const bf* __restrict__ Al, size_t lda,
    const bf* __restrict__ Bh, const bf* __restrict__ Bl, size_t ldb,
    int nktp, AccFrag acc[4][2])
{
    constexpr int ALD = AT ? 136 : 40;   // AT tile: 32x136, else 128x40
    constexpr int BLD = BT ? 136 : 40;
    bf* Ash = (bf*)(smpool);
    bf* Asl = (bf*)(smpool + 10240);
    bf* Bsh = (bf*)(smpool + 20480);
    bf* Bsl = (bf*)(smpool + 30720);

    const int tid = threadIdx.x;
    const int w   = tid >> 5;
    const int wmi = w >> 2, wni = w & 3;

    // loader: each thread moves 2x uint4 (16 bf) per array per chunk
    const int ar = AT ? (tid >> 3) : (tid >> 1);
    const int ac = (AT ? (tid & 7) : (tid & 1)) * 2;   // 8-elem chunk base
    const int br = BT ? (tid >> 3) : (tid >> 1);
    const int bc = (BT ? (tid & 7) : (tid & 1)) * 2;
    const int aso = ar * ALD + ac * 8;
    const int bso = br * BLD + bc * 8;

    auto agof = [&](int kt, int j) -> size_t {
        return AT ? (size_t)(kt * 32 + ar) * lda + (ac + j) * 8
                  : (size_t)ar * lda + kt * 32 + (ac + j) * 8;
    };
    auto bgof = [&](int kt, int j) -> size_t {
        return BT ? (size_t)(kt * 32 + br) * ldb + (bc + j) * 8
                  : (size_t)br * ldb + kt * 32 + (bc + j) * 8;
    };

#pragma unroll
    for (int mt = 0; mt < 4; mt++)
#pragma unroll
        for (int n2 = 0; n2 < 2; n2++)
            wm::fill_fragment(acc[mt][n2], 0.0f);

    using ALay = typename std::conditional<AT, wm::col_major, wm::row_major>::type;
    using BLay = typename std::conditional<BT, wm::row_major, wm::col_major>::type;

    for (int kt = 0; kt < nktp; ++kt) {
        __syncthreads();   // previous chunk fully consumed
#pragma unroll
        for (int j = 0; j < 2; j++) {
            *(uint4*)(&Ash[aso + j * 8]) = *(const uint4*)(Ah + agof(kt, j));
            *(uint4*)(&Asl[aso + j * 8]) = *(const uint4*)(Al + agof(kt, j));
            *(uint4*)(&Bsh[bso + j * 8]) = *(const uint4*)(Bh + bgof(kt, j));
            *(uint4*)(&Bsl[bso + j * 8]) = *(const uint4*)(Bl + bgof(kt, j));
        }
        __syncthreads();

#pragma unroll
        for (int kk = 0; kk < 2; kk++) {
            wm::fragment<wm::matrix_b, 16, 16, 16, bf, BLay> bfh[2], bfl[2];
#pragma unroll
            for (int n2 = 0; n2 < 2; n2++) {
                int n0 = wni * 32 + n2 * 16;
                int off = BT ? (kk * 16 * BLD + n0) : (n0 * BLD + kk * 16);
                wm::load_matrix_sync(bfh[n2], &Bsh[off], BLD);
                wm::load_matrix_sync(bfl[n2], &Bsl[off], BLD);
            }
#pragma unroll
            for (int mt = 0; mt < 4; mt++) {
                wm::fragment<wm::matrix_a, 16, 16, 16, bf, ALay> afh, afl;
                int m0 = wmi * 64 + mt * 16;
                int off = AT ? (kk * 16 * ALD + m0) : (m0 * ALD + kk * 16);
                wm::load_matrix_sync(afh, &Ash[off], ALD);
                wm::load_matrix_sync(afl, &Asl[off], ALD);
#pragma unroll
                for (int n2 = 0; n2 < 2; n2++) {
                    wm::mma_sync(acc[mt][n2], afh, bfh[n2], acc[mt][n2]);
                    wm::mma_sync(acc[mt][n2], afl, bfh[n2], acc[mt][n2]);
                    wm::mma_sync(acc[mt][n2], afh, bfl[n2], acc[mt][n2]);
                }
            }
        }
    }
    __syncthreads();   // protect pool before epilogue aliases it
}

// Epilogue: stage each frag through smem (aliases pool), then scalar writes.
// Exposes: row (0..127 tile-local), col (0..127 tile-local), v (float).
#define EPILOGUE(...)                                                     \
  { float* stg = (float*)(smpool) + (threadIdx.x >> 5) * 320;             \
    const int lane = threadIdx.x & 31;                                    \
    const int w = threadIdx.x >> 5, wm_ = w >> 2, wn_ = w & 3;            \
    for (int mt = 0; mt < 4; mt++)                                        \
      for (int n2 = 0; n2 < 2; n2++) {                                    \
        wm::store_matrix_sync(stg, acc[mt][n2], 20, wm::mem_row_major);   \
        __syncwarp();                                                     \
        _Pragma("unroll")                                                 \
        for (int e = 0; e < 8; e++) {                                     \
          int lr = 2 * e + (lane >> 4); int lc = lane & 15;               \
          int row = wm_ * 64 + mt * 16 + lr;                              \
          int col = wn_ * 32 + n2 * 16 + lc;                              \
          float v = stg[lr * 20 + lc];                                    \
          __VA_ARGS__                                                     \
        }                                                                 \
        __syncwarp();                                                     \
      } }

#define DECL_POOL __shared__ __align__(16) char smpool[POOL_BYTES]

__device__ __forceinline__ void split1(bf* Oh, bf* Ol, size_t idx, float v) {
    bf h = __float2bfloat16(v);
    Oh[idx] = h;
    Ol[idx] = __float2bfloat16(v - __bfloat162float(h));
}
__device__ __forceinline__ void split_store(bf* Oh, bf* Ol, size_t idx,
                                            float v0, float v1) {
    bf h0 = __float2bfloat16(v0), h1 = __float2bfloat16(v1);
    bf2 ph; ph.x = h0; ph.y = h1;
    bf2 pl; pl.x = __float2bfloat16(v0 - __bfloat162float(h0));
            pl.y = __float2bfloat16(v1 - __bfloat162float(h1));
    *(bf2*)(Oh + idx) = ph;
    *(bf2*)(Ol + idx) = pl;
}

// ---------------- conversion / scan ----------------------------------------
__global__ void conv_x_kernel(const float* __restrict__ x) {
    int i = blockIdx.x * 256 + threadIdx.x;       // over NROWS*DIM/4
    int r = i >> 7;
    int d = (i & 127) * 4;
    int tt = r >> 4, bb = r & 15;
    float4 v = *(const float4*)(x + (size_t)(bb * TLEN + tt) * DIM + d);
    size_t o = (size_t)r * DIM + d;
    split_store(g_Xh, g_Xl, o,     v.x, v.y);
    split_store(g_Xh, g_Xl, o + 2, v.z, v.w);
}

__global__ void conv_w_kernel(const float* __restrict__ Wq,
                              const float* __restrict__ Wk,
                              const float* __restrict__ Wv) {
    int i = blockIdx.x * 256 + threadIdx.x;       // over 3*DD2/4
    int z = i >> 16;
    int off = (i & 65535) * 4;
    const float* src = (z == 0) ? Wq : (z == 1) ? Wk : Wv;
    float4 v = *(const float4*)(src + off);
    size_t o = (size_t)z * DD2 + off;
    split_store(g_Wh, g_Wl, o,     v.x, v.y);
    split_store(g_Wh, g_Wl, o + 2, v.z, v.w);
}

__global__ void scan_kernel(const float* __restrict__ mem0) {
    int i4 = (blockIdx.x * 256 + threadIdx.x) * 4;    // over DD2
    float4 acc = *(const float4*)(mem0 + i4);
    for (int g = 0; g < NG; g++) {
        size_t off = (size_t)g * DD2 + i4;
        float4 u = *(const float4*)(g_U + off);
        split_store(g_Sh, g_Sl, off,     acc.x, acc.y);
        split_store(g_Sh, g_Sl, off + 2, acc.z, acc.w);
        acc.x = fmaf(LRW, u.x, acc.x);
        acc.y = fmaf(LRW, u.y, acc.y);
        acc.z = fmaf(LRW, u.z, acc.z);
        acc.w = fmaf(LRW, u.w, acc.w);
    }
}

// ---------------- GEMM kernels ---------------------------------------------
__global__ __launch_bounds__(256, 2) void gemm_qkv_kernel() {
    DECL_POOL;
    int mt0 = blockIdx.x, nt0 = blockIdx.y, z = blockIdx.z;
    const bf* Ah = g_Xh + (size_t)mt0 * 128 * DIM;
    const bf* Al = g_Xl + (size_t)mt0 * 128 * DIM;
    const bf* Bh = g_Wh + (size_t)z * DD2 + (size_t)nt0 * 128 * DIM;
    const bf* Bl = g_Wl + (size_t)z * DD2 + (size_t)nt0 * 128 * DIM;
    AccFrag acc[4][2];
    gemm_core<false, false>(smpool, Ah, Al, DIM, Bh, Bl, DIM, DIM / 32, acc);
    bf* Oh = (z == 0) ? g_Qh : (z == 1) ? g_Kh : g_Vh;
    bf* Ol = (z == 0) ? g_Ql : (z == 1) ? g_Kl : g_Vl;
    EPILOGUE(
        size_t idx = (size_t)(mt0 * 128 + row) * DIM + nt0 * 128 + col;
        split1(Oh, Ol, idx, v);
    )
}

// U_g[d,e] = sum_r V[r,d] K[r,e]   -- A = V read transposed, B = K read NN
__global__ __launch_bounds__(256, 2) void gemm_u_kernel() {
    DECL_POOL;
    int d0 = blockIdx.x * 128, e0 = blockIdx.y * 128, g = blockIdx.z;
    const bf* Ah = g_Vh + (size_t)(g * GROWS) * DIM + d0;
    const bf* Al = g_Vl + (size_t)(g * GROWS) * DIM + d0;
    const bf* Bh = g_Kh + (size_t)(g * GROWS) * DIM + e0;
    const bf* Bl = g_Kl + (size_t)(g * GROWS) * DIM + e0;
    AccFrag acc[4][2];
    gemm_core<true, true>(smpool, Ah, Al, DIM, Bh, Bl, DIM, GROWS / 32, acc);
    float* U = g_U + (size_t)g * DD2;
    EPILOGUE(
        U[(size_t)(d0 + row) * DIM + e0 + col] = v;
    )
}

__global__ __launch_bounds__(256, 2) void gemm_inter_kernel(float* __restrict__ out) {
    DECL_POOL;
    int mt0 = blockIdx.x, nt0 = blockIdx.y;
    int g = mt0 >> 1;
    const bf* Ah = g_Qh + (size_t)mt0 * 128 * DIM;
    const bf* Al = g_Ql + (size_t)mt0 * 128 * DIM;
    const bf* Bh = g_Sh + (size_t)g * DD2 + (size_t)nt0 * 128 * DIM;
    const bf* Bl = g_Sl + (size_t)g * DD2 + (size_t)nt0 * 128 * DIM;
    AccFrag acc[4][2];
    gemm_core<false, false>(smpool, Ah, Al, DIM, Bh, Bl, DIM, DIM / 32, acc);
    EPILOGUE(
        int r = mt0 * 128 + row;
        int tt = r >> 4; int bb = r & 15;
        out[(size_t)(bb * TLEN + tt) * DIM + nt0 * 128 + col] = v;
    )
}

__global__ __launch_bounds__(256, 2) void gemm_score_kernel() {
    DECL_POOL;
    int id = blockIdx.x;                 // 0:(0,0) 1:(1,0) 2:(1,1)
    int ti = (id == 0) ? 0 : 1;
    int tj = (id == 2) ? 1 : 0;
    int g = blockIdx.y;
    const bf* Ah = g_Qh + (size_t)(g * GROWS + ti * 128) * DIM;
    const bf* Al = g_Ql + (size_t)(g * GROWS + ti * 128) * DIM;
    const bf* Bh = g_Kh + (size_t)(g * GROWS + tj * 128) * DIM;
    const bf* Bl = g_Kl + (size_t)(g * GROWS + tj * 128) * DIM;
    AccFrag acc[4][2];
    gemm_core<false, false>(smpool, Ah, Al, DIM, Bh, Bl, DIM, DIM / 32, acc);
    bf* Sch = g_Sch + (size_t)g * GR2;
    bf* Scl = g_Scl + (size_t)g * GR2;
    EPILOGUE(
        int rr = ti * 128 + row;
        int ss = tj * 128 + col;
        float m = ((ss >> 4) <= (rr >> 4)) ? LRW * v : 0.0f;
        split1(Sch, Scl, (size_t)rr * GROWS + ss, m);
    )
}

// out[r,d] += sum_s Sc[r,s] V[s,d]  -- B = V read NN
__global__ __launch_bounds__(256, 2) void gemm_av_kernel(float* __restrict__ out) {
    DECL_POOL;
    int ti = blockIdx.x;                 // 0..1 row tile within group
    int nt0 = blockIdx.y;                // 0..3
    int g = blockIdx.z;
    const bf* Ah = g_Sch + (size_t)g * GR2 + (size_t)ti * 128 * GROWS;
    const bf* Al = g_Scl + (size_t)g * GR2 + (size_t)ti * 128 * GROWS;
    const bf* Bh = g_Vh + (size_t)(g * GROWS) * DIM + nt0 * 128;
    const bf* Bl = g_Vl + (size_t)(g * GROWS) * DIM + nt0 * 128;
    AccFrag acc[4][2];
    gemm_core<false, true>(smpool, Ah, Al, GROWS, Bh, Bl, DIM, 4 * (ti + 1), acc);
    EPILOGUE(
        int r = g * GROWS + ti * 128 + row;
        int tt = r >> 4; int bb = r & 15;
        size_t idx = (size_t)(bb * TLEN + tt) * DIM + nt0 * 128 + col;
        out[idx] += v;
    )
}

// ---------------------------------------------------------------------------
extern "C" void kernel_launch(void* const* d_in, const int* in_sizes, int n_in,
                              void* d_out, int out_size) {
    (void)in_sizes; (void)n_in; (void)out_size;
    const float* x  = (const float*)d_in[0];
    const float* Wq = (const float*)d_in[1];
    const float* Wk = (const float*)d_in[2];
    const float* Wv = (const float*)d_in[3];
    const float* m0 = (const float*)d_in[4];
    float* out = (float*)d_out;

    conv_x_kernel<<<32768, 256>>>(x);
    conv_w_kernel<<<768, 256>>>(Wq, Wk, Wv);
    gemm_qkv_kernel<<<dim3(512, 4, 3), 256>>>();
    gemm_u_kernel<<<dim3(4, 4, 256), 256>>>();
    scan_kernel<<<256, 256>>>(m0);
    gemm_score_kernel<<<dim3(3, 256), 256>>>();
    gemm_inter_kernel<<<dim3(512, 4), 256>>>(out);
    gemm_av_kernel<<<dim3(2, 4, 256), 256>>>(out);
}